// round 4
// baseline (speedup 1.0000x reference)
#include <cuda_runtime.h>
#include <cuda_bf16.h>
#include <math.h>
#include <stdint.h>

// ---------------- problem constants (fixed by setup_inputs) ----------------
#define BATCH     32
#define TT        64
#define NCONT     2048          // B*T
#define CCH       64
#define HH        160
#define WW        160
#define PPTS      32            // NUM_POINTS / STRIDE
#define KCONV     2112          // 66 * 32
#define NEMBD     512
#define QKDIM     1024
#define HEADS     8

// ---------------- scratch (__device__ globals; no runtime alloc) -----------
__device__ float g_cf_in[NCONT * KCONV];   // A matrix for conv GEMM (n, c*32+p)
__device__ float g_cf   [NCONT * NEMBD];   // conv output
__device__ float g_qk   [NCONT * QKDIM];   // q|k
__device__ int   g_mask [NCONT];
__device__ int   g_order[NCONT];
__device__ float g_att_part[4][BATCH * TT * TT];   // split-K attention partials

// ---------------- helpers ---------------------------------------------------
__device__ __forceinline__ float f2tf32(float a) {
    uint32_t u;
    asm("cvt.rna.tf32.f32 %0, %1;" : "=r"(u) : "f"(a));
    return __uint_as_float(u);
}

#define MMA_TF32(C, A, B)                                                    \
    asm volatile(                                                            \
        "mma.sync.aligned.m16n8k8.row.col.f32.tf32.tf32.f32 "                \
        "{%0,%1,%2,%3},{%4,%5,%6,%7},{%8,%9},{%0,%1,%2,%3};"                 \
        : "+f"((C)[0]), "+f"((C)[1]), "+f"((C)[2]), "+f"((C)[3])             \
        : "r"(__float_as_uint((A)[0])), "r"(__float_as_uint((A)[1])),        \
          "r"(__float_as_uint((A)[2])), "r"(__float_as_uint((A)[3])),        \
          "r"(__float_as_uint((B)[0])), "r"(__float_as_uint((B)[1])))

// ---------------- K1: bilinear gather + build conv-GEMM input --------------
__global__ __launch_bounds__(256) void gather_kernel(
    const float* __restrict__ cnn,       // (32,64,160,160)
    const float* __restrict__ contours,  // (2048,128,2)
    const int*   __restrict__ img_idx)   // (2048,)
{
    int n   = blockIdx.x;
    int tid = threadIdx.x;

    __shared__ int   s_off[4][PPTS];
    __shared__ float s_wt [4][PPTS];
    __shared__ float s_x[PPTS], s_y[PPTS];
    __shared__ int   s_b;

    if (tid == 0) s_b = img_idx[n];
    if (tid < PPTS) {
        int p = tid;
        float x = contours[((size_t)n * 128 + p * 4) * 2 + 0];
        float y = contours[((size_t)n * 128 + p * 4) * 2 + 1];
        s_x[p] = x; s_y[p] = y;
        float px = x * 0.25f - 0.5f;     // * (W/w) = 160/640
        float py = y * 0.25f - 0.5f;
        float x0 = floorf(px), y0 = floorf(py);
        float fx = px - x0, fy = py - y0;
        float xs[2] = { x0, x0 + 1.f };
        float ys[2] = { y0, y0 + 1.f };
        float wx[2] = { 1.f - fx, fx };
        float wy[2] = { 1.f - fy, fy };
#pragma unroll
        for (int t = 0; t < 4; t++) {
            float xi = xs[t & 1], yi = ys[t >> 1];
            bool valid = (xi >= 0.f) && (xi < 160.f) && (yi >= 0.f) && (yi < 160.f);
            int xc = (int)fminf(fmaxf(xi, 0.f), 159.f);
            int yc = (int)fminf(fmaxf(yi, 0.f), 159.f);
            s_off[t][p] = yc * WW + xc;
            s_wt [t][p] = valid ? wx[t & 1] * wy[t >> 1] : 0.f;
        }
    }
    __syncthreads();

    int b = s_b;
    float* out = g_cf_in + (size_t)n * KCONV;
    for (int k = tid; k < KCONV; k += 256) {
        int c = k >> 5, p = k & 31;
        float v;
        if (c < CCH) {
            const float* base = cnn + (size_t)(b * CCH + c) * (HH * WW);
            v = s_wt[0][p] * __ldg(base + s_off[0][p])
              + s_wt[1][p] * __ldg(base + s_off[1][p])
              + s_wt[2][p] * __ldg(base + s_off[2][p])
              + s_wt[3][p] * __ldg(base + s_off[3][p]);
        } else if (c == CCH) {
            v = s_x[p] * (1.0f / 640.f);
        } else {
            v = s_y[p] * (1.0f / 640.f);
        }
        out[k] = v;
    }
}

// ---------------- K2: mask dtype probe + prefix-sum order ------------------
__global__ __launch_bounds__(1024) void scan_order_kernel(
    const void* __restrict__ ct01)
{
    __shared__ int sA[NCONT], sB[NCONT];
    __shared__ int flags[2];
    int tid = threadIdx.x;
    if (tid < 2) flags[tid] = 0;
    __syncthreads();
    if (tid < 512) {
        int v = ((const int*)ct01)[tid];
        if (v != 0 && v != 1) flags[0] = 1;
        float f = __int_as_float(v);
        if (!(f == 0.0f || f == 1.0f)) flags[1] = 1;
    }
    __syncthreads();
    int dtype = (flags[0] == 0) ? 0 : ((flags[1] == 0) ? 1 : 2); // 0=i32,1=f32,2=u8

    for (int i = tid; i < NCONT; i += 1024) {
        int m;
        if (dtype == 0)      m = ((const int*)ct01)[i] != 0;
        else if (dtype == 1) m = ((const float*)ct01)[i] != 0.0f;
        else                 m = ((const unsigned char*)ct01)[i] != 0;
        sA[i] = m;
        g_mask[i] = m;
    }
    __syncthreads();

    int* src = sA; int* dst = sB;
    for (int off = 1; off < NCONT; off <<= 1) {
        for (int i = tid; i < NCONT; i += 1024) {
            int v = src[i];
            if (i >= off) v += src[i - off];
            dst[i] = v;
        }
        __syncthreads();
        int* t = src; src = dst; dst = t;
    }
    for (int i = tid; i < NCONT; i += 1024) {
        int o = src[i] - 1;
        o = min(max(o, 0), NCONT - 1);
        g_order[i] = o;
    }
}

// ---------------- K3/K4: 3xTF32 tensor-core NT GEMM ------------------------
// C(MxN) = A(MxK) * B(NxK)^T + epilogue.  BM=128 BN=64 BK=16, 256 thr,
// warp grid 4(M)x2(N), warp tile 32x32 via 2x4 m16n8k8 mma, 2 k-steps.
// A/B split hi/lo (tf32) at smem-fill time; 3 mma passes -> fp32 accuracy.
template <bool POS_EPI>
__global__ __launch_bounds__(256) void gemm_tf32_kernel(
    const float* __restrict__ Bg,
    const float* __restrict__ bias, const float* __restrict__ pos,
    const int* __restrict__ ct_ind, int N, int K)
{
    const int BM = 128, BN = 64, BK = 16;
    __shared__ float2 As2[BM][BK + 1];   // .x = hi, .y = lo
    __shared__ float2 Bs2[BN][BK + 1];

    const float* Ag = POS_EPI ? g_cf_in : g_cf;
    float*       C  = POS_EPI ? g_cf    : g_qk;

    int tid  = threadIdx.x;
    int lane = tid & 31;
    int warp = tid >> 5;
    int warp_m = warp & 3;      // 0..3
    int warp_n = warp >> 2;     // 0..1
    int m_w = warp_m * 32;
    int n_w = warp_n * 32;

    int m0 = blockIdx.y * BM;
    int n0 = blockIdx.x * BN;

    float acc[2][4][4];
#pragma unroll
    for (int i = 0; i < 2; i++)
#pragma unroll
        for (int j = 0; j < 4; j++)
#pragma unroll
            for (int l = 0; l < 4; l++) acc[i][j][l] = 0.f;

    int lr4 = lane >> 2;        // 0..7
    int lk  = lane & 3;         // 0..3

    for (int k0 = 0; k0 < K; k0 += BK) {
        // ---- fill A: 128x16 = 512 float4s, 2 per thread ----
#pragma unroll
        for (int i = 0; i < 2; i++) {
            int idx = i * 256 + tid;          // 0..511
            int r = idx >> 2, q = idx & 3;
            float4 v = *(const float4*)&Ag[(size_t)(m0 + r) * K + k0 + q * 4];
            float h, l;
            h = f2tf32(v.x); l = f2tf32(v.x - h); As2[r][q * 4 + 0] = make_float2(h, l);
            h = f2tf32(v.y); l = f2tf32(v.y - h); As2[r][q * 4 + 1] = make_float2(h, l);
            h = f2tf32(v.z); l = f2tf32(v.z - h); As2[r][q * 4 + 2] = make_float2(h, l);
            h = f2tf32(v.w); l = f2tf32(v.w - h); As2[r][q * 4 + 3] = make_float2(h, l);
        }
        // ---- fill B: 64x16 = 256 float4s, 1 per thread ----
        {
            int r = tid >> 2, q = tid & 3;
            float4 v = *(const float4*)&Bg[(size_t)(n0 + r) * K + k0 + q * 4];
            float h, l;
            h = f2tf32(v.x); l = f2tf32(v.x - h); Bs2[r][q * 4 + 0] = make_float2(h, l);
            h = f2tf32(v.y); l = f2tf32(v.y - h); Bs2[r][q * 4 + 1] = make_float2(h, l);
            h = f2tf32(v.z); l = f2tf32(v.z - h); Bs2[r][q * 4 + 2] = make_float2(h, l);
            h = f2tf32(v.w); l = f2tf32(v.w - h); Bs2[r][q * 4 + 3] = make_float2(h, l);
        }
        __syncthreads();

#pragma unroll
        for (int ks = 0; ks < 2; ks++) {
            int kb = ks * 8;
            float ahi[2][4], alo[2][4];
#pragma unroll
            for (int mt = 0; mt < 2; mt++) {
                int row = m_w + mt * 16 + lr4;
                float2 p0 = As2[row    ][kb + lk    ];
                float2 p1 = As2[row + 8][kb + lk    ];
                float2 p2 = As2[row    ][kb + lk + 4];
                float2 p3 = As2[row + 8][kb + lk + 4];
                ahi[mt][0] = p0.x; ahi[mt][1] = p1.x; ahi[mt][2] = p2.x; ahi[mt][3] = p3.x;
                alo[mt][0] = p0.y; alo[mt][1] = p1.y; alo[mt][2] = p2.y; alo[mt][3] = p3.y;
            }
            float bhi[4][2], blo[4][2];
#pragma unroll
            for (int nt = 0; nt < 4; nt++) {
                int col = n_w + nt * 8 + lr4;
                float2 q0 = Bs2[col][kb + lk    ];
                float2 q1 = Bs2[col][kb + lk + 4];
                bhi[nt][0] = q0.x; bhi[nt][1] = q1.x;
                blo[nt][0] = q0.y; blo[nt][1] = q1.y;
            }
#pragma unroll
            for (int mt = 0; mt < 2; mt++)
#pragma unroll
                for (int nt = 0; nt < 4; nt++) {
                    MMA_TF32(acc[mt][nt], ahi[mt], bhi[nt]);
                    MMA_TF32(acc[mt][nt], ahi[mt], blo[nt]);
                    MMA_TF32(acc[mt][nt], alo[mt], bhi[nt]);
                }
        }
        __syncthreads();
    }

    // ---- epilogue ----
#pragma unroll
    for (int mt = 0; mt < 2; mt++) {
        int row = m_w + mt * 16 + lr4;
        int m = m0 + row;               // and m+8 for c2/c3
        int pb0 = 0, pb1 = 0;
        if (POS_EPI) {
            int i0 = ct_ind[m];
            int i1 = ct_ind[m + 8];
            pb0 = ((i0 / WW) / 10) * 16 + (i0 % WW) / 10;
            pb1 = ((i1 / WW) / 10) * 16 + (i1 % WW) / 10;
        }
#pragma unroll
        for (int nt = 0; nt < 4; nt++) {
            int c = n0 + n_w + nt * 8 + 2 * lk;
            float b0 = bias[c], b1 = bias[c + 1];
            float v0 = acc[mt][nt][0] + b0;
            float v1 = acc[mt][nt][1] + b1;
            float v2 = acc[mt][nt][2] + b0;
            float v3 = acc[mt][nt][3] + b1;
            if (POS_EPI) {
                v0 += pos[(size_t)c * 256 + pb0];
                v1 += pos[(size_t)(c + 1) * 256 + pb0];
                v2 += pos[(size_t)c * 256 + pb1];
                v3 += pos[(size_t)(c + 1) * 256 + pb1];
            }
            *(float2*)&C[(size_t)m * N + c]       = make_float2(v0, v1);
            *(float2*)&C[(size_t)(m + 8) * N + c] = make_float2(v2, v3);
        }
    }
}

// ---------------- K5a: attention partials (split-K over embed dim) ---------
__global__ __launch_bounds__(256) void attn_part_kernel(
    const float* __restrict__ p_w)
{
    int b  = blockIdx.x;
    int dz = blockIdx.y;            // 0..3, chunk of 128 dims
    int tid = threadIdx.x;

    __shared__ float Qs[32][TT + 4];
    __shared__ float Ks[32][TT + 4];
    __shared__ float pw[HEADS];
    __shared__ int s_ord[TT], s_msk[TT];

    if (tid < HEADS) pw[tid] = p_w[tid];
    if (tid < TT) {
        int i = b * TT + tid;
        s_ord[tid] = g_order[i];
        s_msk[tid] = g_mask[i];
    }
    __syncthreads();

    int ty = tid >> 4, tx = tid & 15;
    float acc[4][4] = {};

    int dbeg = dz * 128;
    for (int d0 = dbeg; d0 < dbeg + 128; d0 += 32) {
#pragma unroll
        for (int l = 0; l < 8; l++) {
            int e = tid + l * 256;     // 0..2047
            int t = e >> 5, dd = e & 31;
            int d = d0 + dd;
            float qv = 0.f, kv = 0.f;
            if (s_msk[t]) {
                const float* row = g_qk + (size_t)s_ord[t] * QKDIM;
                qv = row[d] * pw[d >> 6];
                kv = row[NEMBD + d];
            }
            Qs[dd][t] = qv;
            Ks[dd][t] = kv;
        }
        __syncthreads();
#pragma unroll
        for (int dd = 0; dd < 32; dd++) {
            float4 a = *(const float4*)&Qs[dd][ty * 4];
            float4 c = *(const float4*)&Ks[dd][tx * 4];
            acc[0][0] += a.x * c.x; acc[0][1] += a.x * c.y;
            acc[0][2] += a.x * c.z; acc[0][3] += a.x * c.w;
            acc[1][0] += a.y * c.x; acc[1][1] += a.y * c.y;
            acc[1][2] += a.y * c.z; acc[1][3] += a.y * c.w;
            acc[2][0] += a.z * c.x; acc[2][1] += a.z * c.y;
            acc[2][2] += a.z * c.z; acc[2][3] += a.z * c.w;
            acc[3][0] += a.w * c.x; acc[3][1] += a.w * c.y;
            acc[3][2] += a.w * c.z; acc[3][3] += a.w * c.w;
        }
        __syncthreads();
    }

    float* dst = g_att_part[dz] + (size_t)b * (TT * TT);
#pragma unroll
    for (int i = 0; i < 4; i++) {
        int t = ty * 4 + i;
#pragma unroll
        for (int j = 0; j < 4; j++) {
            int s = tx * 4 + j;
            dst[t * TT + s] = acc[i][j];
        }
    }
}

// ---------------- K5b: combine partials + sigmoid ---------------------------
__global__ __launch_bounds__(256) void attn_final_kernel(float* __restrict__ out)
{
    int i = blockIdx.x * 256 + threadIdx.x;   // 0 .. 131071
    float v = (g_att_part[0][i] + g_att_part[1][i]
             + g_att_part[2][i] + g_att_part[3][i]) * 0.125f;
    float sg = 1.f / (1.f + expf(-v));
    if (isnan(sg)) sg = 0.f;
    out[i] = sg;
}

// ---------------- launch ----------------------------------------------------
extern "C" void kernel_launch(void* const* d_in, const int* in_sizes, int n_in,
                              void* d_out, int out_size)
{
    const float* cnn      = (const float*)d_in[0];
    const float* contours = (const float*)d_in[1];
    const void*  ct01     = (const void*) d_in[2];
    const int*   img_idx  = (const int*)  d_in[3];
    const int*   ct_ind   = (const int*)  d_in[4];
    // d_in[5]=h, d_in[6]=w : fixed at 640, hardcoded
    const float* conv_w   = (const float*)d_in[7];   // (512, 2112)
    const float* conv_b   = (const float*)d_in[8];
    const float* attn_w   = (const float*)d_in[9];   // (1024, 512)
    const float* attn_b   = (const float*)d_in[10];
    const float* p_w      = (const float*)d_in[11];  // 8 floats
    const float* pos      = (const float*)d_in[12];  // (512, 16, 16)
    float* out = (float*)d_out;

    scan_order_kernel<<<1, 1024>>>(ct01);
    gather_kernel<<<NCONT, 256>>>(cnn, contours, img_idx);

    {
        dim3 grid(NEMBD / 64, NCONT / 128);      // 8 x 16
        gemm_tf32_kernel<true><<<grid, 256>>>(conv_w, conv_b, pos, ct_ind,
                                              NEMBD, KCONV);
    }
    {
        dim3 grid(QKDIM / 64, NCONT / 128);      // 16 x 16
        gemm_tf32_kernel<false><<<grid, 256>>>(attn_w, attn_b, nullptr, nullptr,
                                               QKDIM, NEMBD);
    }
    {
        dim3 grid(BATCH, 4);
        attn_part_kernel<<<grid, 256>>>(p_w);
    }
    attn_final_kernel<<<BATCH * TT * TT / 256, 256>>>(out);
}

// round 7
// speedup vs baseline: 1.8358x; 1.8358x over previous
#include <cuda_runtime.h>
#include <cuda_bf16.h>
#include <math.h>
#include <stdint.h>

// ---------------- problem constants (fixed by setup_inputs) ----------------
#define BATCH     32
#define TT        64
#define NCONT     2048          // B*T
#define CCH       64
#define HH        160
#define WW        160
#define PPTS      32            // NUM_POINTS / STRIDE
#define KCONV     2112          // 66 * 32
#define NEMBD     512
#define QKDIM     1024
#define HEADS     8

// ---------------- scratch (__device__ globals; no runtime alloc) -----------
__device__ float g_cf_in[NCONT * KCONV];   // A matrix for conv GEMM (n, c*32+p)
__device__ float g_cf   [NCONT * NEMBD];   // conv output
__device__ float g_qk   [NCONT * QKDIM];   // q|k
__device__ int   g_mask [NCONT];
__device__ int   g_order[NCONT];
__device__ float g_att_part[4][BATCH * TT * TT];   // split-K attention partials

// ---------------- helpers ---------------------------------------------------
// pack: low half = bf16(a), high half = bf16(b)
__device__ __forceinline__ uint32_t bf16pair(float a, float b) {
    uint32_t r;
    asm("cvt.rn.bf16x2.f32 %0, %1, %2;" : "=r"(r) : "f"(b), "f"(a));
    return r;
}
__device__ __forceinline__ uint32_t smem_u32(const void* p) {
    uint32_t a;
    asm("{ .reg .u64 t; cvta.to.shared.u64 t, %1; cvt.u32.u64 %0, t; }" : "=r"(a) : "l"(p));
    return a;
}
__device__ __forceinline__ void ldsm4(uint32_t& r0, uint32_t& r1, uint32_t& r2,
                                      uint32_t& r3, uint32_t addr) {
    asm volatile("ldmatrix.sync.aligned.m8n8.x4.shared.b16 {%0,%1,%2,%3}, [%4];"
                 : "=r"(r0), "=r"(r1), "=r"(r2), "=r"(r3) : "r"(addr));
}
__device__ __forceinline__ void sts64(uint32_t a, uint32_t x, uint32_t y) {
    asm volatile("st.shared.v2.b32 [%0], {%1,%2};" :: "r"(a), "r"(x), "r"(y) : "memory");
}

#define MMA_BF16(C, A, B)                                                     \
    asm volatile(                                                             \
        "mma.sync.aligned.m16n8k16.row.col.f32.bf16.bf16.f32 "                \
        "{%0,%1,%2,%3},{%4,%5,%6,%7},{%8,%9},{%0,%1,%2,%3};"                  \
        : "+f"((C)[0]), "+f"((C)[1]), "+f"((C)[2]), "+f"((C)[3])              \
        : "r"((A)[0]), "r"((A)[1]), "r"((A)[2]), "r"((A)[3]),                 \
          "r"((B)[0]), "r"((B)[1]))

// ---------------- K1: bilinear gather + build conv-GEMM input --------------
__global__ __launch_bounds__(256) void gather_kernel(
    const float* __restrict__ cnn,       // (32,64,160,160)
    const float* __restrict__ contours,  // (2048,128,2)
    const int*   __restrict__ img_idx)   // (2048,)
{
    int n   = blockIdx.x;
    int tid = threadIdx.x;

    __shared__ int   s_off[4][PPTS];
    __shared__ float s_wt [4][PPTS];
    __shared__ float s_x[PPTS], s_y[PPTS];
    __shared__ int   s_b;

    if (tid == 0) s_b = img_idx[n];
    if (tid < PPTS) {
        int p = tid;
        float x = contours[((size_t)n * 128 + p * 4) * 2 + 0];
        float y = contours[((size_t)n * 128 + p * 4) * 2 + 1];
        s_x[p] = x; s_y[p] = y;
        float px = x * 0.25f - 0.5f;     // * (W/w) = 160/640
        float py = y * 0.25f - 0.5f;
        float x0 = floorf(px), y0 = floorf(py);
        float fx = px - x0, fy = py - y0;
        float xs[2] = { x0, x0 + 1.f };
        float ys[2] = { y0, y0 + 1.f };
        float wx[2] = { 1.f - fx, fx };
        float wy[2] = { 1.f - fy, fy };
#pragma unroll
        for (int t = 0; t < 4; t++) {
            float xi = xs[t & 1], yi = ys[t >> 1];
            bool valid = (xi >= 0.f) && (xi < 160.f) && (yi >= 0.f) && (yi < 160.f);
            int xc = (int)fminf(fmaxf(xi, 0.f), 159.f);
            int yc = (int)fminf(fmaxf(yi, 0.f), 159.f);
            s_off[t][p] = yc * WW + xc;
            s_wt [t][p] = valid ? wx[t & 1] * wy[t >> 1] : 0.f;
        }
    }
    __syncthreads();

    int b = s_b;
    float* out = g_cf_in + (size_t)n * KCONV;
    for (int k = tid; k < KCONV; k += 256) {
        int c = k >> 5, p = k & 31;
        float v;
        if (c < CCH) {
            const float* base = cnn + (size_t)(b * CCH + c) * (HH * WW);
            v = s_wt[0][p] * __ldg(base + s_off[0][p])
              + s_wt[1][p] * __ldg(base + s_off[1][p])
              + s_wt[2][p] * __ldg(base + s_off[2][p])
              + s_wt[3][p] * __ldg(base + s_off[3][p]);
        } else if (c == CCH) {
            v = s_x[p] * (1.0f / 640.f);
        } else {
            v = s_y[p] * (1.0f / 640.f);
        }
        out[k] = v;
    }
}

// ---------------- K2: mask dtype probe + prefix-sum order ------------------
__global__ __launch_bounds__(1024) void scan_order_kernel(
    const void* __restrict__ ct01)
{
    __shared__ int sA[NCONT], sB[NCONT];
    __shared__ int flags[2];
    int tid = threadIdx.x;
    if (tid < 2) flags[tid] = 0;
    __syncthreads();
    if (tid < 512) {
        int v = ((const int*)ct01)[tid];
        if (v != 0 && v != 1) flags[0] = 1;
        float f = __int_as_float(v);
        if (!(f == 0.0f || f == 1.0f)) flags[1] = 1;
    }
    __syncthreads();
    int dtype = (flags[0] == 0) ? 0 : ((flags[1] == 0) ? 1 : 2); // 0=i32,1=f32,2=u8

    for (int i = tid; i < NCONT; i += 1024) {
        int m;
        if (dtype == 0)      m = ((const int*)ct01)[i] != 0;
        else if (dtype == 1) m = ((const float*)ct01)[i] != 0.0f;
        else                 m = ((const unsigned char*)ct01)[i] != 0;
        sA[i] = m;
        g_mask[i] = m;
    }
    __syncthreads();

    int* src = sA; int* dst = sB;
    for (int off = 1; off < NCONT; off <<= 1) {
        for (int i = tid; i < NCONT; i += 1024) {
            int v = src[i];
            if (i >= off) v += src[i - off];
            dst[i] = v;
        }
        __syncthreads();
        int* t = src; src = dst; dst = t;
    }
    for (int i = tid; i < NCONT; i += 1024) {
        int o = src[i] - 1;
        o = min(max(o, 0), NCONT - 1);
        g_order[i] = o;
    }
}

// ---------------- K3/K4: 3xBF16 tensor-core NT GEMM (ldmatrix) -------------
// C(MxN) = A(MxK)*B(NxK)^T + epilogue. BM=128 BN=64 BK=16, 256 thr,
// warps 4(M)x2(N), warp tile 32x32 via 2x4 m16n8k16 bf16 mma, 3 passes
// (hi*hi + hi*lo + lo*hi) for ~fp32 accuracy. Rows padded to 24 bf16 (48B)
// so ldmatrix phases are bank-conflict-free. Double-buffered.
#define BKE   16          // k elements per slice
#define LDK   24          // padded row length (bf16 elems) = 48 bytes

template <bool POS_EPI>
__global__ __launch_bounds__(256) void gemm_bf16_kernel(
    const float* __restrict__ Bg,
    const float* __restrict__ bias, const float* __restrict__ pos,
    const int* __restrict__ ct_ind, int Nn, int K)
{
    __shared__ __align__(16) __nv_bfloat16 sAhi[2][128 * LDK];
    __shared__ __align__(16) __nv_bfloat16 sAlo[2][128 * LDK];
    __shared__ __align__(16) __nv_bfloat16 sBhi[2][64 * LDK];
    __shared__ __align__(16) __nv_bfloat16 sBlo[2][64 * LDK];

    const float* Ag = POS_EPI ? g_cf_in : g_cf;
    float*       C  = POS_EPI ? g_cf    : g_qk;

    int tid  = threadIdx.x;
    int lane = tid & 31;
    int warp = tid >> 5;
    int m_w  = (warp & 3) * 32;
    int n_w  = (warp >> 2) * 32;
    int m0 = blockIdx.y * 128;
    int n0 = blockIdx.x * 64;

    float acc[2][4][4];
#pragma unroll
    for (int i = 0; i < 2; i++)
#pragma unroll
        for (int j = 0; j < 4; j++)
#pragma unroll
            for (int l = 0; l < 4; l++) acc[i][j][l] = 0.f;

    // fill indices
    int ar = 0, aq = 0, br = 0, bq = 0;
    ar = tid >> 2; aq = tid & 3;            // A: rows 0..63 (i=0), 64..127 (i=1)
    br = tid >> 2; bq = tid & 3;            // B: 64 rows x 4 quads = 256 threads

    // ---- fill helper (lambda-free, macro-ish via function) ----
    auto fill_stage = [&](int s, int c) {
        // A: 128 rows x 16 floats = 512 float4; 2 per thread
#pragma unroll
        for (int i = 0; i < 2; i++) {
            int row = ar + i * 64;
            const float4 v = __ldg((const float4*)&Ag[(size_t)(m0 + row) * K + c * BKE + aq * 4]);
            float h0f, h1f, h2f, h3f;
            h0f = __bfloat162float(__float2bfloat16(v.x));
            h1f = __bfloat162float(__float2bfloat16(v.y));
            h2f = __bfloat162float(__float2bfloat16(v.z));
            h3f = __bfloat162float(__float2bfloat16(v.w));
            uint32_t hA = bf16pair(h0f, h1f), hB = bf16pair(h2f, h3f);
            uint32_t lA = bf16pair(v.x - h0f, v.y - h1f), lB = bf16pair(v.z - h2f, v.w - h3f);
            uint32_t off = (uint32_t)(row * LDK + aq * 4) * 2;   // bytes
            sts64(smem_u32(&sAhi[s][0]) + off, hA, hB);
            sts64(smem_u32(&sAlo[s][0]) + off, lA, lB);
        }
        // B: 64 rows x 16 floats = 256 float4; 1 per thread
        {
            const float4 v = __ldg((const float4*)&Bg[(size_t)(n0 + br) * K + c * BKE + bq * 4]);
            float h0f, h1f, h2f, h3f;
            h0f = __bfloat162float(__float2bfloat16(v.x));
            h1f = __bfloat162float(__float2bfloat16(v.y));
            h2f = __bfloat162float(__float2bfloat16(v.z));
            h3f = __bfloat162float(__float2bfloat16(v.w));
            uint32_t hA = bf16pair(h0f, h1f), hB = bf16pair(h2f, h3f);
            uint32_t lA = bf16pair(v.x - h0f, v.y - h1f), lB = bf16pair(v.z - h2f, v.w - h3f);
            uint32_t off = (uint32_t)(br * LDK + bq * 4) * 2;
            sts64(smem_u32(&sBhi[s][0]) + off, hA, hB);
            sts64(smem_u32(&sBlo[s][0]) + off, lA, lB);
        }
    };

    const int NC = K / BKE;
    fill_stage(0, 0);
    __syncthreads();

    // ldmatrix lane addressing (byte offsets within a tile)
    uint32_t a_row = (uint32_t)(lane & 15);          // 0..15
    uint32_t a_kb  = (uint32_t)(lane >> 4) * 16;     // 0 or 16 bytes (k+8)
    uint32_t b_n   = (uint32_t)(((lane >> 3) & 2) * 4 + (lane & 7)); // 0..7 / 8..15
    uint32_t b_kb  = (uint32_t)((lane >> 3) & 1) * 16;

    for (int c = 0; c < NC; c++) {
        int s = c & 1;

        uint32_t ahi[2][4], alo[2][4], bhi[4][2], blo[4][2];
        {
            uint32_t baseAh = smem_u32(&sAhi[s][0]);
            uint32_t baseAl = smem_u32(&sAlo[s][0]);
#pragma unroll
            for (int mt = 0; mt < 2; mt++) {
                uint32_t off = (uint32_t)((m_w + mt * 16 + a_row) * LDK) * 2 + a_kb;
                ldsm4(ahi[mt][0], ahi[mt][1], ahi[mt][2], ahi[mt][3], baseAh + off);
                ldsm4(alo[mt][0], alo[mt][1], alo[mt][2], alo[mt][3], baseAl + off);
            }
            uint32_t baseBh = smem_u32(&sBhi[s][0]);
            uint32_t baseBl = smem_u32(&sBlo[s][0]);
#pragma unroll
            for (int nh = 0; nh < 2; nh++) {   // each x4 covers two n8 tiles
                uint32_t off = (uint32_t)((n_w + nh * 16 + b_n) * LDK) * 2 + b_kb;
                ldsm4(bhi[nh * 2][0], bhi[nh * 2][1], bhi[nh * 2 + 1][0], bhi[nh * 2 + 1][1],
                      baseBh + off);
                ldsm4(blo[nh * 2][0], blo[nh * 2][1], blo[nh * 2 + 1][0], blo[nh * 2 + 1][1],
                      baseBl + off);
            }
        }

        if (c + 1 < NC) fill_stage(1 - s, c + 1);

#pragma unroll
        for (int mt = 0; mt < 2; mt++)
#pragma unroll
            for (int nt = 0; nt < 4; nt++) {
                MMA_BF16(acc[mt][nt], ahi[mt], bhi[nt]);
                MMA_BF16(acc[mt][nt], ahi[mt], blo[nt]);
                MMA_BF16(acc[mt][nt], alo[mt], bhi[nt]);
            }
        __syncthreads();
    }

    // ---- epilogue (same C-fragment layout as m16n8 f32) ----
    int lr4 = lane >> 2;        // 0..7
    int lk  = lane & 3;         // 0..3
#pragma unroll
    for (int mt = 0; mt < 2; mt++) {
        int m = m0 + m_w + mt * 16 + lr4;
        int pb0 = 0, pb1 = 0;
        if (POS_EPI) {
            int i0 = ct_ind[m];
            int i1 = ct_ind[m + 8];
            pb0 = ((i0 / WW) / 10) * 16 + (i0 % WW) / 10;
            pb1 = ((i1 / WW) / 10) * 16 + (i1 % WW) / 10;
        }
#pragma unroll
        for (int nt = 0; nt < 4; nt++) {
            int cc = n0 + n_w + nt * 8 + 2 * lk;
            float b0 = bias[cc], b1 = bias[cc + 1];
            float v0 = acc[mt][nt][0] + b0;
            float v1 = acc[mt][nt][1] + b1;
            float v2 = acc[mt][nt][2] + b0;
            float v3 = acc[mt][nt][3] + b1;
            if (POS_EPI) {
                v0 += pos[(size_t)cc * 256 + pb0];
                v1 += pos[(size_t)(cc + 1) * 256 + pb0];
                v2 += pos[(size_t)cc * 256 + pb1];
                v3 += pos[(size_t)(cc + 1) * 256 + pb1];
            }
            *(float2*)&C[(size_t)m * Nn + cc]       = make_float2(v0, v1);
            *(float2*)&C[(size_t)(m + 8) * Nn + cc] = make_float2(v2, v3);
        }
    }
}

// ---------------- K5a: attention partials (split-K over embed dim) ---------
__global__ __launch_bounds__(256) void attn_part_kernel(
    const float* __restrict__ p_w)
{
    int b  = blockIdx.x;
    int dz = blockIdx.y;            // 0..3, chunk of 128 dims
    int tid = threadIdx.x;

    __shared__ float Qs[32][TT + 4];
    __shared__ float Ks[32][TT + 4];
    __shared__ float pw[HEADS];
    __shared__ int s_ord[TT], s_msk[TT];

    if (tid < HEADS) pw[tid] = p_w[tid];
    if (tid < TT) {
        int i = b * TT + tid;
        s_ord[tid] = g_order[i];
        s_msk[tid] = g_mask[i];
    }
    __syncthreads();

    int ty = tid >> 4, tx = tid & 15;
    float acc[4][4] = {};

    int dbeg = dz * 128;
    for (int d0 = dbeg; d0 < dbeg + 128; d0 += 32) {
#pragma unroll
        for (int l = 0; l < 8; l++) {
            int e = tid + l * 256;     // 0..2047
            int t = e >> 5, dd = e & 31;
            int d = d0 + dd;
            float qv = 0.f, kv = 0.f;
            if (s_msk[t]) {
                const float* row = g_qk + (size_t)s_ord[t] * QKDIM;
                qv = row[d] * pw[d >> 6];
                kv = row[NEMBD + d];
            }
            Qs[dd][t] = qv;
            Ks[dd][t] = kv;
        }
        __syncthreads();
#pragma unroll
        for (int dd = 0; dd < 32; dd++) {
            float4 a = *(const float4*)&Qs[dd][ty * 4];
            float4 c = *(const float4*)&Ks[dd][tx * 4];
            acc[0][0] += a.x * c.x; acc[0][1] += a.x * c.y;
            acc[0][2] += a.x * c.z; acc[0][3] += a.x * c.w;
            acc[1][0] += a.y * c.x; acc[1][1] += a.y * c.y;
            acc[1][2] += a.y * c.z; acc[1][3] += a.y * c.w;
            acc[2][0] += a.z * c.x; acc[2][1] += a.z * c.y;
            acc[2][2] += a.z * c.z; acc[2][3] += a.z * c.w;
            acc[3][0] += a.w * c.x; acc[3][1] += a.w * c.y;
            acc[3][2] += a.w * c.z; acc[3][3] += a.w * c.w;
        }
        __syncthreads();
    }

    float* dst = g_att_part[dz] + (size_t)b * (TT * TT);
#pragma unroll
    for (int i = 0; i < 4; i++) {
        int t = ty * 4 + i;
#pragma unroll
        for (int j = 0; j < 4; j++) {
            int s = tx * 4 + j;
            dst[t * TT + s] = acc[i][j];
        }
    }
}

// ---------------- K5b: combine partials + sigmoid ---------------------------
__global__ __launch_bounds__(256) void attn_final_kernel(float* __restrict__ out)
{
    int i = blockIdx.x * 256 + threadIdx.x;   // 0 .. 131071
    float v = (g_att_part[0][i] + g_att_part[1][i]
             + g_att_part[2][i] + g_att_part[3][i]) * 0.125f;
    float sg = 1.f / (1.f + expf(-v));
    if (isnan(sg)) sg = 0.f;
    out[i] = sg;
}

// ---------------- launch ----------------------------------------------------
extern "C" void kernel_launch(void* const* d_in, const int* in_sizes, int n_in,
                              void* d_out, int out_size)
{
    const float* cnn      = (const float*)d_in[0];
    const float* contours = (const float*)d_in[1];
    const void*  ct01     = (const void*) d_in[2];
    const int*   img_idx  = (const int*)  d_in[3];
    const int*   ct_ind   = (const int*)  d_in[4];
    // d_in[5]=h, d_in[6]=w : fixed at 640, hardcoded
    const float* conv_w   = (const float*)d_in[7];   // (512, 2112)
    const float* conv_b   = (const float*)d_in[8];
    const float* attn_w   = (const float*)d_in[9];   // (1024, 512)
    const float* attn_b   = (const float*)d_in[10];
    const float* p_w      = (const float*)d_in[11];  // 8 floats
    const float* pos      = (const float*)d_in[12];  // (512, 16, 16)
    float* out = (float*)d_out;

    scan_order_kernel<<<1, 1024>>>(ct01);
    gather_kernel<<<NCONT, 256>>>(cnn, contours, img_idx);

    {
        dim3 grid(NEMBD / 64, NCONT / 128);      // 8 x 16 = 128 CTAs
        gemm_bf16_kernel<true><<<grid, 256>>>(conv_w, conv_b, pos, ct_ind,
                                              NEMBD, KCONV);
    }
    {
        dim3 grid(QKDIM / 64, NCONT / 128);      // 16 x 16 = 256 CTAs
        gemm_bf16_kernel<false><<<grid, 256>>>(attn_w, attn_b, nullptr, nullptr,
                                               QKDIM, NEMBD);
    }
    {
        dim3 grid(BATCH, 4);
        attn_part_kernel<<<grid, 256>>>(p_w);
    }
    attn_final_kernel<<<BATCH * TT * TT / 256, 256>>>(out);
}

// round 9
// speedup vs baseline: 2.5251x; 1.3755x over previous
#include <cuda_runtime.h>
#include <cuda_bf16.h>
#include <math.h>
#include <stdint.h>

// ---------------- problem constants (fixed by setup_inputs) ----------------
#define BATCH     32
#define TT        64
#define NCONT     2048          // B*T
#define CCH       64
#define HH        160
#define WW        160
#define PPTS      32            // NUM_POINTS / STRIDE
#define KCONV     2112          // 66 * 32
#define NEMBD     512
#define QKDIM     1024
#define HEADS     8

// ---------------- scratch (__device__ globals; no runtime alloc) -----------
// bf16 hi/lo pairs, stored via uint4 arrays to guarantee 16B alignment.
__device__ uint4 g_ga_hi4[NCONT * KCONV / 8];    // gathered A  (2048 x 2112)
__device__ uint4 g_ga_lo4[NCONT * KCONV / 8];
__device__ uint4 g_cf_hi4[NCONT * NEMBD / 8];    // conv output (2048 x 512)
__device__ uint4 g_cf_lo4[NCONT * NEMBD / 8];
__device__ uint4 g_wc_hi4[NEMBD * KCONV / 8];    // conv_w      (512 x 2112)
__device__ uint4 g_wc_lo4[NEMBD * KCONV / 8];
__device__ uint4 g_wa_hi4[QKDIM * NEMBD / 8];    // attn_w      (1024 x 512)
__device__ uint4 g_wa_lo4[QKDIM * NEMBD / 8];
__device__ float g_qk   [NCONT * QKDIM];         // q|k (f32)
__device__ int   g_mask [NCONT];
__device__ int   g_order[NCONT];
__device__ float g_att_part[4][BATCH * TT * TT]; // split-K attention partials

// ---------------- helpers ---------------------------------------------------
// packed bf16x2: low half = bf16(a), high half = bf16(b)
__device__ __forceinline__ uint32_t bf16pair(float a, float b) {
    uint32_t r;
    asm("cvt.rn.bf16x2.f32 %0, %1, %2;" : "=r"(r) : "f"(b), "f"(a));
    return r;
}
__device__ __forceinline__ uint32_t smem_u32(const void* p) {
    uint32_t a;
    asm("{ .reg .u64 t; cvta.to.shared.u64 t, %1; cvt.u32.u64 %0, t; }" : "=r"(a) : "l"(p));
    return a;
}
__device__ __forceinline__ void ldsm4(uint32_t& r0, uint32_t& r1, uint32_t& r2,
                                      uint32_t& r3, uint32_t addr) {
    asm volatile("ldmatrix.sync.aligned.m8n8.x4.shared.b16 {%0,%1,%2,%3}, [%4];"
                 : "=r"(r0), "=r"(r1), "=r"(r2), "=r"(r3) : "r"(addr));
}
#define CP16(dst, src) \
    asm volatile("cp.async.cg.shared.global [%0], [%1], 16;" :: "r"(dst), "l"(src))
#define CP_COMMIT() asm volatile("cp.async.commit_group;" ::: "memory")
#define CP_WAIT1()  asm volatile("cp.async.wait_group 1;" ::: "memory")

#define MMA_BF16(C, A, B)                                                     \
    asm volatile(                                                             \
        "mma.sync.aligned.m16n8k16.row.col.f32.bf16.bf16.f32 "                \
        "{%0,%1,%2,%3},{%4,%5,%6,%7},{%8,%9},{%0,%1,%2,%3};"                  \
        : "+f"((C)[0]), "+f"((C)[1]), "+f"((C)[2]), "+f"((C)[3])              \
        : "r"((A)[0]), "r"((A)[1]), "r"((A)[2]), "r"((A)[3]),                 \
          "r"((B)[0]), "r"((B)[1]))

// ---------------- K0a/K0b: weight f32 -> bf16 hi/lo split ------------------
__global__ __launch_bounds__(256) void convert_wc_kernel(const float* __restrict__ src)
{
    int i = blockIdx.x * 256 + threadIdx.x;
    const int n4 = NEMBD * KCONV / 4;
    if (i >= n4) return;
    float4 v = __ldg((const float4*)src + i);
    float h0 = __bfloat162float(__float2bfloat16(v.x));
    float h1 = __bfloat162float(__float2bfloat16(v.y));
    float h2 = __bfloat162float(__float2bfloat16(v.z));
    float h3 = __bfloat162float(__float2bfloat16(v.w));
    ((uint2*)g_wc_hi4)[i] = make_uint2(bf16pair(h0, h1), bf16pair(h2, h3));
    ((uint2*)g_wc_lo4)[i] = make_uint2(bf16pair(v.x - h0, v.y - h1),
                                       bf16pair(v.z - h2, v.w - h3));
}
__global__ __launch_bounds__(256) void convert_wa_kernel(const float* __restrict__ src)
{
    int i = blockIdx.x * 256 + threadIdx.x;
    const int n4 = QKDIM * NEMBD / 4;
    if (i >= n4) return;
    float4 v = __ldg((const float4*)src + i);
    float h0 = __bfloat162float(__float2bfloat16(v.x));
    float h1 = __bfloat162float(__float2bfloat16(v.y));
    float h2 = __bfloat162float(__float2bfloat16(v.z));
    float h3 = __bfloat162float(__float2bfloat16(v.w));
    ((uint2*)g_wa_hi4)[i] = make_uint2(bf16pair(h0, h1), bf16pair(h2, h3));
    ((uint2*)g_wa_lo4)[i] = make_uint2(bf16pair(v.x - h0, v.y - h1),
                                       bf16pair(v.z - h2, v.w - h3));
}

// ---------------- K1: bilinear gather -> bf16 hi/lo A matrix ---------------
__global__ __launch_bounds__(256) void gather_kernel(
    const float* __restrict__ cnn,       // (32,64,160,160)
    const float* __restrict__ contours,  // (2048,128,2)
    const int*   __restrict__ img_idx)   // (2048,)
{
    int n   = blockIdx.x;
    int z   = blockIdx.y;                // 0/1 : k-range half
    int tid = threadIdx.x;

    __shared__ int   s_off[4][PPTS];
    __shared__ float s_wt [4][PPTS];
    __shared__ float s_x[PPTS], s_y[PPTS];
    __shared__ int   s_b;

    if (tid == 0) s_b = img_idx[n];
    if (tid < PPTS) {
        int p = tid;
        float x = contours[((size_t)n * 128 + p * 4) * 2 + 0];
        float y = contours[((size_t)n * 128 + p * 4) * 2 + 1];
        s_x[p] = x; s_y[p] = y;
        float px = x * 0.25f - 0.5f;     // * (W/w) = 160/640
        float py = y * 0.25f - 0.5f;
        float x0 = floorf(px), y0 = floorf(py);
        float fx = px - x0, fy = py - y0;
        float xs[2] = { x0, x0 + 1.f };
        float ys[2] = { y0, y0 + 1.f };
        float wx[2] = { 1.f - fx, fx };
        float wy[2] = { 1.f - fy, fy };
#pragma unroll
        for (int t = 0; t < 4; t++) {
            float xi = xs[t & 1], yi = ys[t >> 1];
            bool valid = (xi >= 0.f) && (xi < 160.f) && (yi >= 0.f) && (yi < 160.f);
            int xc = (int)fminf(fmaxf(xi, 0.f), 159.f);
            int yc = (int)fminf(fmaxf(yi, 0.f), 159.f);
            s_off[t][p] = yc * WW + xc;
            s_wt [t][p] = valid ? wx[t & 1] * wy[t >> 1] : 0.f;
        }
    }
    __syncthreads();

    int b = s_b;
    __nv_bfloat16* out_hi = (__nv_bfloat16*)g_ga_hi4 + (size_t)n * KCONV;
    __nv_bfloat16* out_lo = (__nv_bfloat16*)g_ga_lo4 + (size_t)n * KCONV;
    int kend = (z + 1) * (KCONV / 2);
    for (int k = z * (KCONV / 2) + tid; k < kend; k += 256) {
        int c = k >> 5, p = k & 31;
        float v;
        if (c < CCH) {
            const float* base = cnn + (size_t)(b * CCH + c) * (HH * WW);
            v = s_wt[0][p] * __ldg(base + s_off[0][p])
              + s_wt[1][p] * __ldg(base + s_off[1][p])
              + s_wt[2][p] * __ldg(base + s_off[2][p])
              + s_wt[3][p] * __ldg(base + s_off[3][p]);
        } else if (c == CCH) {
            v = s_x[p] * (1.0f / 640.f);
        } else {
            v = s_y[p] * (1.0f / 640.f);
        }
        __nv_bfloat16 h = __float2bfloat16(v);
        out_hi[k] = h;
        out_lo[k] = __float2bfloat16(v - __bfloat162float(h));
    }
}

// ---------------- K2: mask dtype probe + prefix-sum order ------------------
__global__ __launch_bounds__(1024) void scan_order_kernel(
    const void* __restrict__ ct01)
{
    __shared__ int sA[NCONT], sB[NCONT];
    __shared__ int flags[2];
    int tid = threadIdx.x;
    if (tid < 2) flags[tid] = 0;
    __syncthreads();
    if (tid < 512) {
        int v = ((const int*)ct01)[tid];
        if (v != 0 && v != 1) flags[0] = 1;
        float f = __int_as_float(v);
        if (!(f == 0.0f || f == 1.0f)) flags[1] = 1;
    }
    __syncthreads();
    int dtype = (flags[0] == 0) ? 0 : ((flags[1] == 0) ? 1 : 2); // 0=i32,1=f32,2=u8

    for (int i = tid; i < NCONT; i += 1024) {
        int m;
        if (dtype == 0)      m = ((const int*)ct01)[i] != 0;
        else if (dtype == 1) m = ((const float*)ct01)[i] != 0.0f;
        else                 m = ((const unsigned char*)ct01)[i] != 0;
        sA[i] = m;
        g_mask[i] = m;
    }
    __syncthreads();

    int* src = sA; int* dst = sB;
    for (int off = 1; off < NCONT; off <<= 1) {
        for (int i = tid; i < NCONT; i += 1024) {
            int v = src[i];
            if (i >= off) v += src[i - off];
            dst[i] = v;
        }
        __syncthreads();
        int* t = src; src = dst; dst = t;
    }
    for (int i = tid; i < NCONT; i += 1024) {
        int o = src[i] - 1;
        o = min(max(o, 0), NCONT - 1);
        g_order[i] = o;
    }
}

// ---------------- K3/K4: 3xBF16 GEMM, cp.async double-buffer ---------------
// C(MxN) = A(MxK)*B(NxK)^T + epilogue. BM=128 BN=64 BK=16, 256 thr, 2 CTA/SM.
// Stage (12KB): Ahi 4K | Alo 4K | Bhi 2K | Blo 2K. Rows 32B, chunk-swizzled:
// byte_off(row, j) = row*32 + ((j ^ ((row>>2)&1)) * 16)  -> ldmatrix conflict-free.
#define OFF_AHI 0
#define OFF_ALO 4096
#define OFF_BHI 8192
#define OFF_BLO 10240
#define STAGEB  12288

template <bool CONV>
__global__ __launch_bounds__(256, 2) void gemm_cp_kernel(
    const float* __restrict__ bias, const float* __restrict__ pos,
    const int* __restrict__ ct_ind)
{
    const int K  = CONV ? KCONV : NEMBD;
    const int Nn = CONV ? NEMBD : QKDIM;
    const __nv_bfloat16* Ah = (const __nv_bfloat16*)(CONV ? g_ga_hi4 : g_cf_hi4);
    const __nv_bfloat16* Al = (const __nv_bfloat16*)(CONV ? g_ga_lo4 : g_cf_lo4);
    const __nv_bfloat16* Bh = (const __nv_bfloat16*)(CONV ? g_wc_hi4 : g_wa_hi4);
    const __nv_bfloat16* Bl = (const __nv_bfloat16*)(CONV ? g_wc_lo4 : g_wa_lo4);

    __shared__ __align__(128) char sm[2][STAGEB];

    int tid  = threadIdx.x;
    int lane = tid & 31;
    int warp = tid >> 5;
    int m_w  = (warp & 3) * 32;
    int n_w  = (warp >> 2) * 32;
    int m0 = blockIdx.y * 128;
    int n0 = blockIdx.x * 64;

    // per-thread prefetch coordinates
    int a_row = tid >> 1, a_j = tid & 1;                 // A: 128 rows x 2 chunks
    int t2 = tid & 127;
    int b_row = t2 >> 1, b_j = t2 & 1;                   // B: 64 rows x 2 chunks
    const __nv_bfloat16* Bsel = (tid < 128) ? Bh : Bl;
    uint32_t b_dst_off = (tid < 128) ? OFF_BHI : OFF_BLO;
    uint32_t a_sw = (uint32_t)(a_row * 32 + ((a_j ^ ((a_row >> 2) & 1)) * 16));
    uint32_t b_sw = (uint32_t)(b_row * 32 + ((b_j ^ ((b_row >> 2) & 1)) * 16));
    const __nv_bfloat16* a_hi_src = Ah + (size_t)(m0 + a_row) * K + a_j * 8;
    const __nv_bfloat16* a_lo_src = Al + (size_t)(m0 + a_row) * K + a_j * 8;
    const __nv_bfloat16* b_src    = Bsel + (size_t)(n0 + b_row) * K + b_j * 8;

    float acc[2][4][4];
#pragma unroll
    for (int i = 0; i < 2; i++)
#pragma unroll
        for (int j = 0; j < 4; j++)
#pragma unroll
            for (int l = 0; l < 4; l++) acc[i][j][l] = 0.f;

    const int NC = K / 16;

    // prologue: fill both stages
#pragma unroll
    for (int pc = 0; pc < 2; pc++) {
        uint32_t base = smem_u32(&sm[pc][0]);
        CP16(base + OFF_AHI + a_sw, a_hi_src + pc * 16);
        CP16(base + OFF_ALO + a_sw, a_lo_src + pc * 16);
        CP16(base + b_dst_off + b_sw, b_src + pc * 16);
        CP_COMMIT();
    }

    // ldmatrix lane coords
    int la_r = lane & 15, la_k = lane >> 4;
    int lb_n = (((lane >> 3) & 2) << 2) | (lane & 7);
    int lb_k = (lane >> 3) & 1;

    for (int c = 0; c < NC; c++) {
        int s = c & 1;
        CP_WAIT1();
        __syncthreads();

        uint32_t ahi[2][4], alo[2][4], bhi[4][2], blo[4][2];
        uint32_t base = smem_u32(&sm[s][0]);
#pragma unroll
        for (int mt = 0; mt < 2; mt++) {
            int row = m_w + mt * 16 + la_r;
            uint32_t off = (uint32_t)(row * 32 + ((la_k ^ ((row >> 2) & 1)) * 16));
            ldsm4(ahi[mt][0], ahi[mt][1], ahi[mt][2], ahi[mt][3], base + OFF_AHI + off);
            ldsm4(alo[mt][0], alo[mt][1], alo[mt][2], alo[mt][3], base + OFF_ALO + off);
        }
#pragma unroll
        for (int nh = 0; nh < 2; nh++) {
            int row = n_w + nh * 16 + lb_n;
            uint32_t off = (uint32_t)(row * 32 + ((lb_k ^ ((row >> 2) & 1)) * 16));
            ldsm4(bhi[nh*2][0], bhi[nh*2][1], bhi[nh*2+1][0], bhi[nh*2+1][1],
                  base + OFF_BHI + off);
            ldsm4(blo[nh*2][0], blo[nh*2][1], blo[nh*2+1][0], blo[nh*2+1][1],
                  base + OFF_BLO + off);
        }
        __syncthreads();

        if (c + 2 < NC) {
            CP16(base + OFF_AHI + a_sw, a_hi_src + (c + 2) * 16);
            CP16(base + OFF_ALO + a_sw, a_lo_src + (c + 2) * 16);
            CP16(base + b_dst_off + b_sw, b_src + (c + 2) * 16);
        }
        CP_COMMIT();

#pragma unroll
        for (int mt = 0; mt < 2; mt++)
#pragma unroll
            for (int nt = 0; nt < 4; nt++) {
                MMA_BF16(acc[mt][nt], ahi[mt], bhi[nt]);
                MMA_BF16(acc[mt][nt], ahi[mt], blo[nt]);
                MMA_BF16(acc[mt][nt], alo[mt], bhi[nt]);
            }
    }

    // ---- epilogue ----
    int lr4 = lane >> 2;        // 0..7
    int lk  = lane & 3;         // 0..3
#pragma unroll
    for (int mt = 0; mt < 2; mt++) {
        int m = m0 + m_w + mt * 16 + lr4;
        int pb0 = 0, pb1 = 0;
        if (CONV) {
            int i0 = ct_ind[m];
            int i1 = ct_ind[m + 8];
            pb0 = ((i0 / WW) / 10) * 16 + (i0 % WW) / 10;
            pb1 = ((i1 / WW) / 10) * 16 + (i1 % WW) / 10;
        }
#pragma unroll
        for (int nt = 0; nt < 4; nt++) {
            int cc = n0 + n_w + nt * 8 + 2 * lk;
            float b0 = bias[cc], b1 = bias[cc + 1];
            float v0 = acc[mt][nt][0] + b0;
            float v1 = acc[mt][nt][1] + b1;
            float v2 = acc[mt][nt][2] + b0;
            float v3 = acc[mt][nt][3] + b1;
            if (CONV) {
                v0 += pos[(size_t)cc * 256 + pb0];
                v1 += pos[(size_t)(cc + 1) * 256 + pb0];
                v2 += pos[(size_t)cc * 256 + pb1];
                v3 += pos[(size_t)(cc + 1) * 256 + pb1];
                __nv_bfloat16* cf_hi = (__nv_bfloat16*)g_cf_hi4;
                __nv_bfloat16* cf_lo = (__nv_bfloat16*)g_cf_lo4;
                float h0 = __bfloat162float(__float2bfloat16(v0));
                float h1 = __bfloat162float(__float2bfloat16(v1));
                float h2 = __bfloat162float(__float2bfloat16(v2));
                float h3 = __bfloat162float(__float2bfloat16(v3));
                *(uint32_t*)&cf_hi[(size_t)m * NEMBD + cc]       = bf16pair(h0, h1);
                *(uint32_t*)&cf_lo[(size_t)m * NEMBD + cc]       = bf16pair(v0 - h0, v1 - h1);
                *(uint32_t*)&cf_hi[(size_t)(m + 8) * NEMBD + cc] = bf16pair(h2, h3);
                *(uint32_t*)&cf_lo[(size_t)(m + 8) * NEMBD + cc] = bf16pair(v2 - h2, v3 - h3);
            } else {
                *(float2*)&g_qk[(size_t)m * QKDIM + cc]       = make_float2(v0, v1);
                *(float2*)&g_qk[(size_t)(m + 8) * QKDIM + cc] = make_float2(v2, v3);
            }
        }
    }
}

// ---------------- K5a: attention partials (split-K over embed dim) ---------
__global__ __launch_bounds__(256) void attn_part_kernel(
    const float* __restrict__ p_w)
{
    int b  = blockIdx.x;
    int dz = blockIdx.y;            // 0..3, chunk of 128 dims
    int tid = threadIdx.x;

    __shared__ float Qs[32][TT + 4];
    __shared__ float Ks[32][TT + 4];
    __shared__ float pw[HEADS];
    __shared__ int s_ord[TT], s_msk[TT];

    if (tid < HEADS) pw[tid] = p_w[tid];
    if (tid < TT) {
        int i = b * TT + tid;
        s_ord[tid] = g_order[i];
        s_msk[tid] = g_mask[i];
    }
    __syncthreads();

    int ty = tid >> 4, tx = tid & 15;
    float acc[4][4] = {};

    int dbeg = dz * 128;
    for (int d0 = dbeg; d0 < dbeg + 128; d0 += 32) {
#pragma unroll
        for (int l = 0; l < 8; l++) {
            int e = tid + l * 256;     // 0..2047
            int t = e >> 5, dd = e & 31;
            int d = d0 + dd;
            float qv = 0.f, kv = 0.f;
            if (s_msk[t]) {
                const float* row = g_qk + (size_t)s_ord[t] * QKDIM;
                qv = row[d] * pw[d >> 6];
                kv = row[NEMBD + d];
            }
            Qs[dd][t] = qv;
            Ks[dd][t] = kv;
        }
        __syncthreads();
#pragma unroll
        for (int dd = 0; dd < 32; dd++) {
            float4 a = *(const float4*)&Qs[dd][ty * 4];
            float4 c = *(const float4*)&Ks[dd][tx * 4];
            acc[0][0] += a.x * c.x; acc[0][1] += a.x * c.y;
            acc[0][2] += a.x * c.z; acc[0][3] += a.x * c.w;
            acc[1][0] += a.y * c.x; acc[1][1] += a.y * c.y;
            acc[1][2] += a.y * c.z; acc[1][3] += a.y * c.w;
            acc[2][0] += a.z * c.x; acc[2][1] += a.z * c.y;
            acc[2][2] += a.z * c.z; acc[2][3] += a.z * c.w;
            acc[3][0] += a.w * c.x; acc[3][1] += a.w * c.y;
            acc[3][2] += a.w * c.z; acc[3][3] += a.w * c.w;
        }
        __syncthreads();
    }

    float* dst = g_att_part[dz] + (size_t)b * (TT * TT);
#pragma unroll
    for (int i = 0; i < 4; i++) {
        int t = ty * 4 + i;
#pragma unroll
        for (int j = 0; j < 4; j++) {
            int s = tx * 4 + j;
            dst[t * TT + s] = acc[i][j];
        }
    }
}

// ---------------- K5b: combine partials + sigmoid ---------------------------
__global__ __launch_bounds__(256) void attn_final_kernel(float* __restrict__ out)
{
    int i = blockIdx.x * 256 + threadIdx.x;   // 0 .. 131071
    float v = (g_att_part[0][i] + g_att_part[1][i]
             + g_att_part[2][i] + g_att_part[3][i]) * 0.125f;
    float sg = 1.f / (1.f + expf(-v));
    if (isnan(sg)) sg = 0.f;
    out[i] = sg;
}

// ---------------- launch ----------------------------------------------------
extern "C" void kernel_launch(void* const* d_in, const int* in_sizes, int n_in,
                              void* d_out, int out_size)
{
    const float* cnn      = (const float*)d_in[0];
    const float* contours = (const float*)d_in[1];
    const void*  ct01     = (const void*) d_in[2];
    const int*   img_idx  = (const int*)  d_in[3];
    const int*   ct_ind   = (const int*)  d_in[4];
    // d_in[5]=h, d_in[6]=w : fixed at 640, hardcoded
    const float* conv_w   = (const float*)d_in[7];   // (512, 2112)
    const float* conv_b   = (const float*)d_in[8];
    const float* attn_w   = (const float*)d_in[9];   // (1024, 512)
    const float* attn_b   = (const float*)d_in[10];
    const float* p_w      = (const float*)d_in[11];  // 8 floats
    const float* pos      = (const float*)d_in[12];  // (512, 16, 16)
    float* out = (float*)d_out;

    scan_order_kernel<<<1, 1024>>>(ct01);
    convert_wc_kernel<<<(NEMBD * KCONV / 4 + 255) / 256, 256>>>(conv_w);
    convert_wa_kernel<<<(QKDIM * NEMBD / 4 + 255) / 256, 256>>>(attn_w);
    gather_kernel<<<dim3(NCONT, 2), 256>>>(cnn, contours, img_idx);

    {
        dim3 grid(NEMBD / 64, NCONT / 128);      // 8 x 16 = 128 CTAs
        gemm_cp_kernel<true><<<grid, 256>>>(conv_b, pos, ct_ind);
    }
    {
        dim3 grid(QKDIM / 64, NCONT / 128);      // 16 x 16 = 256 CTAs
        gemm_cp_kernel<false><<<grid, 256>>>(attn_b, nullptr, nullptr);
    }
    {
        dim3 grid(BATCH, 4);
        attn_part_kernel<<<grid, 256>>>(p_w);
    }
    attn_final_kernel<<<BATCH * TT * TT / 256, 256>>>(out);
}